// round 14
// baseline (speedup 1.0000x reference)
#include <cuda_runtime.h>

// Piecewise-linear log-sigmoid approximation (table interp).
// inputs: vals[64*2048*2048] f32, x[65] f32 (uniform linspace), y[65] f32
// output: f32 same shape.
//
// Semantics (matches jax reference):
//   v <  x[0]  -> v
//   v >= x[64] -> 0
//   else out = y[i] + (v - x[i]) * slope[i],  i = floor((v-x0)/h) clamped
//
// Persistent single-wave grid (148 SMs x 4 CTAs), grid-stride, ILP=8 float4
// per thread per iteration, front-batched streaming loads, 32-bit indexing.
// Full iterations are unconditional; one guarded tail pass handles the
// non-divisible remainder.

#define NBP  65
#define NSEG 64
#define ILP  8
#define THREADS 256
#define BLOCKS  592   // 148 SMs * 4 CTAs -> exactly one wave (8 warps/CTA, 32 warps/SM)

__global__ __launch_bounds__(THREADS) void logsig_kernel(
        const float* __restrict__ vals,
        const float* __restrict__ xs,
        const float* __restrict__ ys,
        float* __restrict__ out,
        unsigned int n4, unsigned int nfull)
{
    // Per-segment affine coefficients: r = c.x + c.y * v
    __shared__ float2 coef[NSEG];
    __shared__ float s_x0, s_xlast, s_invh;

    const unsigned int t = threadIdx.x;
    if (t < NSEG) {
        float x0 = xs[t];
        float x1 = xs[t + 1];
        float y0 = ys[t];
        float y1 = ys[t + 1];
        float slope = (y1 - y0) / (x1 - x0);
        coef[t] = make_float2(fmaf(-x0, slope, y0), slope);
    }
    if (t == 0) {
        float a = xs[0];
        float b = xs[NBP - 1];
        s_x0    = a;
        s_xlast = b;
        s_invh  = (float)NSEG / (b - a);
    }
    __syncthreads();

    const float x0    = s_x0;
    const float xlast = s_xlast;
    const float invh  = s_invh;

    const float4* __restrict__ in4  = reinterpret_cast<const float4*>(vals);
    float4* __restrict__       out4 = reinterpret_cast<float4*>(out);

    const unsigned int stride = (unsigned int)gridDim.x * (THREADS * ILP);
    unsigned int base = blockIdx.x * (THREADS * ILP) + t;

    // ---- full (unconditional) iterations ----
    for (unsigned int it = 0; it < nfull; it++, base += stride) {
        float4 v[ILP];
        #pragma unroll
        for (int j = 0; j < ILP; j++)
            v[j] = __ldcs(&in4[base + j * THREADS]);

        float4 o[ILP];
        #pragma unroll
        for (int j = 0; j < ILP; j++) {
            float vv[4] = {v[j].x, v[j].y, v[j].z, v[j].w};
            float oo[4];
            #pragma unroll
            for (int k = 0; k < 4; k++) {
                float val = vv[k];
                int idx = (int)((val - x0) * invh);
                idx = max(0, min(idx, NSEG - 1));
                float2 c = coef[idx];
                float r = fmaf(c.y, val, c.x);
                r = (val <  x0)    ? val  : r;
                r = (val >= xlast) ? 0.0f : r;
                oo[k] = r;
            }
            o[j].x = oo[0]; o[j].y = oo[1]; o[j].z = oo[2]; o[j].w = oo[3];
        }

        #pragma unroll
        for (int j = 0; j < ILP; j++)
            __stcs(&out4[base + j * THREADS], o[j]);
    }

    // ---- guarded tail pass (remainder < one grid-stride) ----
    #pragma unroll
    for (int j = 0; j < ILP; j++) {
        unsigned int i = base + (unsigned int)j * THREADS;
        if (i < n4) {
            float4 v = __ldcs(&in4[i]);
            float vv[4] = {v.x, v.y, v.z, v.w};
            float oo[4];
            #pragma unroll
            for (int k = 0; k < 4; k++) {
                float val = vv[k];
                int idx = (int)((val - x0) * invh);
                idx = max(0, min(idx, NSEG - 1));
                float2 c = coef[idx];
                float r = fmaf(c.y, val, c.x);
                r = (val <  x0)    ? val  : r;
                r = (val >= xlast) ? 0.0f : r;
                oo[k] = r;
            }
            float4 o;
            o.x = oo[0]; o.y = oo[1]; o.z = oo[2]; o.w = oo[3];
            __stcs(&out4[i], o);
        }
    }
}

extern "C" void kernel_launch(void* const* d_in, const int* in_sizes, int n_in,
                              void* d_out, int out_size)
{
    const float* vals = (const float*)d_in[0];
    const float* xs   = (const float*)d_in[1];
    const float* ys   = (const float*)d_in[2];
    float* out        = (float*)d_out;

    unsigned int n4 = (unsigned int)(out_size / 4);      // 2^26 float4s
    unsigned int stride = BLOCKS * THREADS * ILP;        // 1,212,416 float4s
    unsigned int nfull = n4 / stride;                    // 55 full grid-iters

    logsig_kernel<<<BLOCKS, THREADS>>>(vals, xs, ys, out, n4, nfull);
}

// round 15
// speedup vs baseline: 1.1577x; 1.1577x over previous
#include <cuda_runtime.h>

// Piecewise-linear log-sigmoid approximation (table interp).
// inputs: vals[64*2048*2048] f32, x[65] f32 (uniform linspace), y[65] f32
// output: f32 same shape.
//
// Semantics (matches jax reference):
//   v <  x[0]  -> v
//   v >= x[64] -> 0
//   else out = y[i] + (v - x[i]) * slope[i],  i = floor((v-x0)/h) clamped
//
// Geometry of the best kernel (4096 blocks x 256 thr, grid-stride, exact
// trip count, streaming hints, 32-bit indexing) + software-pipelined
// double buffer: iteration i+1's loads are issued BEFORE iteration i's
// compute+stores, so the read stream never drains behind the write stream.

#define NBP  65
#define NSEG 64
#define ILP  4          // float4s per thread per iteration (x2 buffers live)
#define THREADS 256
#define BLOCKS  4096
// per grid-iter float4s: 4096*256*4 = 2^22 ; n4 = 2^26 -> exactly 16 iters.

__global__ __launch_bounds__(THREADS) void logsig_kernel(
        const float* __restrict__ vals,
        const float* __restrict__ xs,
        const float* __restrict__ ys,
        float* __restrict__ out,
        unsigned int niter)
{
    // Per-segment affine coefficients: r = c.x + c.y * v
    __shared__ float2 coef[NSEG];
    __shared__ float s_x0, s_xlast, s_invh;

    const unsigned int t = threadIdx.x;
    if (t < NSEG) {
        float x0 = xs[t];
        float x1 = xs[t + 1];
        float y0 = ys[t];
        float y1 = ys[t + 1];
        float slope = (y1 - y0) / (x1 - x0);
        coef[t] = make_float2(fmaf(-x0, slope, y0), slope);
    }
    if (t == 0) {
        float a = xs[0];
        float b = xs[NBP - 1];
        s_x0    = a;
        s_xlast = b;
        s_invh  = (float)NSEG / (b - a);
    }
    __syncthreads();

    const float x0    = s_x0;
    const float xlast = s_xlast;
    const float invh  = s_invh;

    const float4* __restrict__ in4  = reinterpret_cast<const float4*>(vals);
    float4* __restrict__       out4 = reinterpret_cast<float4*>(out);

    const unsigned int stride = (unsigned int)gridDim.x * (THREADS * ILP);
    unsigned int base = blockIdx.x * (THREADS * ILP) + t;

    // Prologue: load iteration 0
    float4 cur[ILP];
    #pragma unroll
    for (int j = 0; j < ILP; j++)
        cur[j] = __ldcs(&in4[base + j * THREADS]);

    for (unsigned int it = 0; it < niter; it++) {
        unsigned int nbase = base + stride;

        // Prefetch next iteration's loads BEFORE this iteration's stores.
        // Clamp the prefetch address on the last iteration (harmless reload).
        unsigned int pbase = (it + 1 < niter) ? nbase : base;
        float4 nxt[ILP];
        #pragma unroll
        for (int j = 0; j < ILP; j++)
            nxt[j] = __ldcs(&in4[pbase + j * THREADS]);

        // Compute + store current
        #pragma unroll
        for (int j = 0; j < ILP; j++) {
            float vv[4] = {cur[j].x, cur[j].y, cur[j].z, cur[j].w};
            float oo[4];
            #pragma unroll
            for (int k = 0; k < 4; k++) {
                float val = vv[k];
                int idx = (int)((val - x0) * invh);
                idx = max(0, min(idx, NSEG - 1));
                float2 c = coef[idx];
                float r = fmaf(c.y, val, c.x);
                r = (val <  x0)    ? val  : r;
                r = (val >= xlast) ? 0.0f : r;
                oo[k] = r;
            }
            float4 o;
            o.x = oo[0]; o.y = oo[1]; o.z = oo[2]; o.w = oo[3];
            __stcs(&out4[base + j * THREADS], o);
        }

        #pragma unroll
        for (int j = 0; j < ILP; j++)
            cur[j] = nxt[j];
        base = nbase;
    }
}

extern "C" void kernel_launch(void* const* d_in, const int* in_sizes, int n_in,
                              void* d_out, int out_size)
{
    const float* vals = (const float*)d_in[0];
    const float* xs   = (const float*)d_in[1];
    const float* ys   = (const float*)d_in[2];
    float* out        = (float*)d_out;

    unsigned int n4 = (unsigned int)(out_size / 4);      // 2^26 float4s
    unsigned int per_iter = BLOCKS * THREADS * ILP;      // 2^22 float4s
    unsigned int niter = (n4 + per_iter - 1) / per_iter; // 16 for this shape

    logsig_kernel<<<BLOCKS, THREADS>>>(vals, xs, ys, out, niter);
}